// round 4
// baseline (speedup 1.0000x reference)
#include <cuda_runtime.h>
#include <cstdint>

#define BB 8
#define HH 128
#define WW 128

__device__ float g_xT[BB*HH*WW*64];   // NHWC copy of x (emitted by k_offset)
__device__ float g_off[BB*HH*WW*18];  // offsets [b][y][x][18]
__device__ float g_w[4608];           // deform weights [k][g][cig][o8]

typedef unsigned long long ull;
static __device__ __forceinline__ ull pk2(float lo, float hi){
    ull r; asm("mov.b64 %0, {%1, %2};" : "=l"(r) : "f"(lo), "f"(hi)); return r;
}
static __device__ __forceinline__ void unpk2(ull v, float& lo, float& hi){
    asm("mov.b64 {%0, %1}, %2;" : "=f"(lo), "=f"(hi) : "l"(v));
}
static __device__ __forceinline__ ull fma2(ull a, ull b, ull c){
    ull d; asm("fma.rn.f32x2 %0, %1, %2, %3;" : "=l"(d) : "l"(a), "l"(b), "l"(c)); return d;
}

// ---------------------------------------------------------------
// Kernel 0: transpose deform weights dw[o][cig][k] -> g_w[k][g][cig][o8]
// ---------------------------------------------------------------
__global__ void k_wprep(const float* __restrict__ dw)
{
    for (int i = threadIdx.x; i < 4608; i += 512){
        float v = __ldg(&dw[i]);
        int o = i / 72, r = i - o*72;
        int cig = r / 9, k = r - cig*9;
        g_w[((k*8 + (o>>3))*8 + cig)*8 + (o&7)] = v;
    }
}

// ---------------------------------------------------------------
// Kernel 1: offset conv 64->18 (3x3) + bias + PReLU -> g_off,
// plus NHWC emit of x -> g_xT.
// 128 thr = 32x16 px tile, 4 px/thread. 8-channel chunks.
// Weight rows padded to 10 ull (80B) -> LDS.128-friendly.
// ---------------------------------------------------------------
__global__ __launch_bounds__(128, 4) void k_offset(const float* __restrict__ x,
                                                   const float* __restrict__ ow,
                                                   const float* __restrict__ ob,
                                                   const float* __restrict__ pa)
{
    __shared__ float tile[8*18*34];              // [c][r(18)][col(34)]
    __shared__ __align__(16) ull wch[720];       // [(c*9+k)][10]: 9 op-pairs + pad

    int tid = threadIdx.x;
    int ty = tid >> 3, txq = (tid & 7) * 4;
    int x0 = blockIdx.x*32, y0 = blockIdx.y*16, b = blockIdx.z;

    ull acc[4][9];
#pragma unroll
    for (int op = 0; op < 9; ++op){
        ull b2 = pk2(__ldg(&ob[2*op]), __ldg(&ob[2*op+1]));
#pragma unroll
        for (int e = 0; e < 4; ++e) acc[e][op] = b2;
    }

    for (int ch = 0; ch < 8; ++ch){
        int c0 = ch*8;
        __syncthreads();
        // weights: coalesced gmem read, scattered STS
        for (int i = tid; i < 1296; i += 128){
            int oc = i / 72, r = i - oc*72;          // r = c*9+k
            float v = __ldg(&ow[oc*576 + c0*9 + r]);
            reinterpret_cast<float*>(wch)[(r*10 + (oc>>1))*2 + (oc&1)] = v;
        }
        // input tile with zero halo
        for (int i = tid; i < 4896; i += 128){
            int c = i / 612, rr = i - c*612;
            int r = rr / 34, col = rr - r*34;
            int gy = y0 - 1 + r, gx = x0 - 1 + col;
            float v = 0.f;
            if ((unsigned)gy < 128u && (unsigned)gx < 128u)
                v = __ldg(&x[((size_t)(b*64 + c0 + c)*128 + gy)*128 + gx]);
            tile[i] = v;
        }
        __syncthreads();

        // NHWC emit
#pragma unroll
        for (int e = 0; e < 4; ++e){
            int base = (ty+1)*34 + (txq+1+e);
            float4 lo4, hi4;
            lo4.x = tile[0*612+base]; lo4.y = tile[1*612+base];
            lo4.z = tile[2*612+base]; lo4.w = tile[3*612+base];
            hi4.x = tile[4*612+base]; hi4.y = tile[5*612+base];
            hi4.z = tile[6*612+base]; hi4.w = tile[7*612+base];
            float4* dst = reinterpret_cast<float4*>(
                g_xT + ((size_t)(b*128 + y0+ty)*128 + x0+txq+e)*64 + c0);
            dst[0] = lo4; dst[1] = hi4;
        }

        // conv accumulate: 4 px share every weight load
        for (int c = 0; c < 8; ++c){
#pragma unroll
            for (int ky = 0; ky < 3; ++ky){
                int rbase = c*612 + (ty+ky)*34 + txq;
                float2 a0 = *reinterpret_cast<const float2*>(&tile[rbase]);
                float2 a1 = *reinterpret_cast<const float2*>(&tile[rbase+2]);
                float2 a2 = *reinterpret_cast<const float2*>(&tile[rbase+4]);
                float v[6] = {a0.x, a0.y, a1.x, a1.y, a2.x, a2.y};
#pragma unroll
                for (int kx = 0; kx < 3; ++kx){
                    const ull* wp = &wch[(c*9 + ky*3 + kx)*10];
                    ull vv[4];
#pragma unroll
                    for (int e = 0; e < 4; ++e) vv[e] = pk2(v[kx+e], v[kx+e]);
#pragma unroll
                    for (int op = 0; op < 9; ++op){
                        ull w = wp[op];
#pragma unroll
                        for (int e = 0; e < 4; ++e)
                            acc[e][op] = fma2(vv[e], w, acc[e][op]);
                    }
                }
            }
        }
    }

    float a = __ldg(&pa[0]);
#pragma unroll
    for (int e = 0; e < 4; ++e){
        float2* dst = reinterpret_cast<float2*>(
            g_off + ((size_t)(b*128 + y0+ty)*128 + x0+txq+e)*18);
#pragma unroll
        for (int op = 0; op < 9; ++op){
            float lo, hi;
            unpk2(acc[e][op], lo, hi);
            lo = lo > 0.f ? lo : a*lo;
            hi = hi > 0.f ? hi : a*hi;
            dst[op] = make_float2(lo, hi);
        }
    }
}

// ---------------------------------------------------------------
// Kernel 2: deformable grouped conv. Block 512 thr = full 128-px row.
//  A) warp = 2px x 16 quads (j=0..3): per-lane bilinear recompute
//     (no shfl), coalesced float4 corner gathers, STS.128.
//  B) warp = (group, half), lane -> pixels p0=half*64+lane, p1=p0+32:
//     uniform LDG.128 weights from g_w, private 8-cig accumulation.
// ---------------------------------------------------------------
__global__ __launch_bounds__(512) void k_deform(const float* __restrict__ db,
                                                float* __restrict__ out)
{
    __shared__ __align__(16) float s_buf[128*68];   // samples [p][68] / out [o][132]

    int tid = threadIdx.x;
    int lane = tid & 31, wid = tid >> 5;
    int b = blockIdx.y, y = blockIdx.x;

    int q = lane & 15, ph = lane >> 4;          // phase-A identity
    int g = wid & 7, half = wid >> 3;           // phase-B identity
    int p0 = half*64 + lane, p1 = p0 + 32;

    const float4* xb = reinterpret_cast<const float4*>(g_xT) + (size_t)b*(128*128*16);
    const float* offrow = g_off + ((size_t)(b*128 + y)*128)*18;

    ull acc[8] = {0,0,0,0,0,0,0,0};

#pragma unroll 1
    for (int k = 0; k < 9; ++k){
        int kyo = k/3 - 1, kxo = k - (k/3)*3 - 1;
        // ---- phase A ----
#pragma unroll
        for (int j = 0; j < 4; ++j){
            int p = wid*8 + j*2 + ph;
            float2 d = __ldg(reinterpret_cast<const float2*>(offrow + p*18) + k);
            float py  = (float)y + (float)kyo + d.x;
            float pxx = (float)p + (float)kxo + d.y;
            float y0f = floorf(py), x0f = floorf(pxx);
            float fy = py - y0f, fx = pxx - x0f;
            float vy0 = (y0f >=  0.f && y0f <= 127.f) ? 1.f : 0.f;
            float vy1 = (y0f >= -1.f && y0f <= 126.f) ? 1.f : 0.f;
            float vx0 = (x0f >=  0.f && x0f <= 127.f) ? 1.f : 0.f;
            float vx1 = (x0f >= -1.f && x0f <= 126.f) ? 1.f : 0.f;
            float w00 = (1.f-fy)*(1.f-fx)*vy0*vx0;
            float w01 = (1.f-fy)*fx*vy0*vx1;
            float w10 = fy*(1.f-fx)*vy1*vx0;
            float w11 = fy*fx*vy1*vx1;
            int y0i = (int)y0f, x0i = (int)x0f;
            int yc0 = min(max(y0i,   0), 127), yc1 = min(max(y0i+1, 0), 127);
            int xc0 = min(max(x0i,   0), 127), xc1 = min(max(x0i+1, 0), 127);
            float4 c00 = __ldg(&xb[(yc0*128 + xc0)*16 + q]);
            float4 c01 = __ldg(&xb[(yc0*128 + xc1)*16 + q]);
            float4 c10 = __ldg(&xb[(yc1*128 + xc0)*16 + q]);
            float4 c11 = __ldg(&xb[(yc1*128 + xc1)*16 + q]);
            float4 s;
            s.x = w00*c00.x + w01*c01.x + w10*c10.x + w11*c11.x;
            s.y = w00*c00.y + w01*c01.y + w10*c10.y + w11*c11.y;
            s.z = w00*c00.z + w01*c01.z + w10*c10.z + w11*c11.z;
            s.w = w00*c00.w + w01*c01.w + w10*c10.w + w11*c11.w;
            *reinterpret_cast<float4*>(&s_buf[p*68 + 4*q]) = s;
        }
        __syncthreads();
        // ---- phase B ----
        {
            const ulonglong2* wk = reinterpret_cast<const ulonglong2*>(g_w + (k*8 + g)*64);
            float4 s0a = *reinterpret_cast<const float4*>(&s_buf[p0*68 + g*8]);
            float4 s0b = *reinterpret_cast<const float4*>(&s_buf[p0*68 + g*8 + 4]);
            float4 s1a = *reinterpret_cast<const float4*>(&s_buf[p1*68 + g*8]);
            float4 s1b = *reinterpret_cast<const float4*>(&s_buf[p1*68 + g*8 + 4]);
            float sm0[8] = {s0a.x,s0a.y,s0a.z,s0a.w, s0b.x,s0b.y,s0b.z,s0b.w};
            float sm1[8] = {s1a.x,s1a.y,s1a.z,s1a.w, s1b.x,s1b.y,s1b.z,s1b.w};
#pragma unroll
            for (int cig = 0; cig < 8; ++cig){
                ulonglong2 wab = __ldg(&wk[cig*2]);
                ulonglong2 wcd = __ldg(&wk[cig*2+1]);
                ull vv0 = pk2(sm0[cig], sm0[cig]);
                ull vv1 = pk2(sm1[cig], sm1[cig]);
                acc[0] = fma2(vv0, wab.x, acc[0]);
                acc[1] = fma2(vv0, wab.y, acc[1]);
                acc[2] = fma2(vv0, wcd.x, acc[2]);
                acc[3] = fma2(vv0, wcd.y, acc[3]);
                acc[4] = fma2(vv1, wab.x, acc[4]);
                acc[5] = fma2(vv1, wab.y, acc[5]);
                acc[6] = fma2(vv1, wcd.x, acc[6]);
                acc[7] = fma2(vv1, wcd.y, acc[7]);
            }
        }
        __syncthreads();
    }

    // stage outputs [o][132] and coalesced NCHW writeback
#pragma unroll
    for (int op = 0; op < 4; ++op){
        float lo, hi;
        unpk2(acc[op], lo, hi);
        s_buf[(g*8 + 2*op    )*132 + p0] = lo;
        s_buf[(g*8 + 2*op + 1)*132 + p0] = hi;
        unpk2(acc[4+op], lo, hi);
        s_buf[(g*8 + 2*op    )*132 + p1] = lo;
        s_buf[(g*8 + 2*op + 1)*132 + p1] = hi;
    }
    __syncthreads();
    for (int i = tid; i < 2048; i += 512){
        int o = i >> 5, p4 = (i & 31)*4;
        float bias = __ldg(&db[o]);
        float4 v = *reinterpret_cast<const float4*>(&s_buf[o*132 + p4]);
        v.x += bias; v.y += bias; v.z += bias; v.w += bias;
        *reinterpret_cast<float4*>(
            &out[((size_t)(b*64 + o)*128 + y)*128 + p4]) = v;
    }
}

extern "C" void kernel_launch(void* const* d_in, const int* in_sizes, int n_in,
                              void* d_out, int out_size)
{
    const float* x  = (const float*)d_in[0];
    const float* ow = (const float*)d_in[1];
    const float* ob = (const float*)d_in[2];
    const float* pa = (const float*)d_in[3];
    const float* dw = (const float*)d_in[4];
    const float* db = (const float*)d_in[5];
    float* out = (float*)d_out;

    k_wprep<<<1, 512>>>(dw);
    k_offset<<<dim3(4, 8, 8), 128>>>(x, ow, ob, pa);
    k_deform<<<dim3(128, 8), 512>>>(db, out);
}

// round 5
// speedup vs baseline: 1.1298x; 1.1298x over previous
#include <cuda_runtime.h>
#include <cstdint>

#define BB 8
#define HH 128
#define WW 128

__device__ float  g_xT[BB*HH*WW*64];        // NHWC copy of x
__device__ float4 g_bw[BB*HH*9*WW];         // bilinear corner weights [b][y][k][x]
__device__ unsigned g_bi[BB*HH*9*WW];       // packed lin00 | lin11<<16

typedef unsigned long long ull;
static __device__ __forceinline__ ull pk2(float lo, float hi){
    ull r; asm("mov.b64 %0, {%1, %2};" : "=l"(r) : "f"(lo), "f"(hi)); return r;
}
static __device__ __forceinline__ void unpk2(ull v, float& lo, float& hi){
    asm("mov.b64 {%0, %1}, %2;" : "=f"(lo), "=f"(hi) : "l"(v));
}
static __device__ __forceinline__ ull fma2(ull a, ull b, ull c){
    ull d; asm("fma.rn.f32x2 %0, %1, %2, %3;" : "=l"(d) : "l"(a), "l"(b), "l"(c)); return d;
}

// ---------------------------------------------------------------
// Kernel 1: offset conv 64->18 (3x3) + bias + PReLU, then epilogue
// converts offsets to bilinear params (g_bw, g_bi). Also emits
// NHWC x -> g_xT. 256 thr = 32x16 px tile, 2 px/thread.
// ---------------------------------------------------------------
__global__ __launch_bounds__(256) void k_offset(const float* __restrict__ x,
                                                const float* __restrict__ ow,
                                                const float* __restrict__ ob,
                                                const float* __restrict__ pa)
{
    __shared__ float tile[8*18*34];               // [c][r(18)][col(34)]
    __shared__ __align__(16) ull wch[720];        // [(c*9+k)][10]: 9 op-pairs + pad

    int tid = threadIdx.x;
    int ty = tid >> 4, txq = (tid & 15) * 2;
    int x0 = blockIdx.x*32, y0 = blockIdx.y*16, b = blockIdx.z;

    ull acc0[9], acc1[9];
#pragma unroll
    for (int op = 0; op < 9; ++op){
        ull b2 = pk2(__ldg(&ob[2*op]), __ldg(&ob[2*op+1]));
        acc0[op] = b2; acc1[op] = b2;
    }

    for (int ch = 0; ch < 8; ++ch){
        int c0 = ch*8;
        __syncthreads();
        // weights: coalesced gmem read, scattered STS into padded rows
        for (int i = tid; i < 1296; i += 256){
            int oc = i / 72, r = i - oc*72;            // r = c*9+k
            float v = __ldg(&ow[oc*576 + c0*9 + r]);
            reinterpret_cast<float*>(wch)[(r*10 + (oc>>1))*2 + (oc&1)] = v;
        }
        // input tile with zero halo
        for (int i = tid; i < 4896; i += 256){
            int c = i / 612, rr = i - c*612;
            int r = rr / 34, col = rr - r*34;
            int gy = y0 - 1 + r, gx = x0 - 1 + col;
            float v = 0.f;
            if ((unsigned)gy < 128u && (unsigned)gx < 128u)
                v = __ldg(&x[((size_t)(b*64 + c0 + c)*128 + gy)*128 + gx]);
            tile[i] = v;
        }
        __syncthreads();

        // NHWC emit
#pragma unroll
        for (int e = 0; e < 2; ++e){
            int base = (ty+1)*34 + (txq+1+e);
            float4 lo4, hi4;
            lo4.x = tile[0*612+base]; lo4.y = tile[1*612+base];
            lo4.z = tile[2*612+base]; lo4.w = tile[3*612+base];
            hi4.x = tile[4*612+base]; hi4.y = tile[5*612+base];
            hi4.z = tile[6*612+base]; hi4.w = tile[7*612+base];
            float4* dst = reinterpret_cast<float4*>(
                g_xT + ((size_t)(b*128 + y0+ty)*128 + x0+txq+e)*64 + c0);
            dst[0] = lo4; dst[1] = hi4;
        }

        // conv accumulate: 2 px share each weight load (LDS.128 pairs)
        for (int c = 0; c < 8; ++c){
#pragma unroll
            for (int ky = 0; ky < 3; ++ky){
                int rbase = c*612 + (ty+ky)*34 + txq;
                float2 va = *reinterpret_cast<const float2*>(&tile[rbase]);
                float2 vb = *reinterpret_cast<const float2*>(&tile[rbase+2]);
                float v[4] = {va.x, va.y, vb.x, vb.y};
#pragma unroll
                for (int kx = 0; kx < 3; ++kx){
                    const ulonglong2* wp2 = reinterpret_cast<const ulonglong2*>(
                        &wch[(c*9 + ky*3 + kx)*10]);
                    ulonglong2 w01 = wp2[0], w23 = wp2[1], w45 = wp2[2], w67 = wp2[3];
                    ull w8 = wch[(c*9 + ky*3 + kx)*10 + 8];
                    ull vv0 = pk2(v[kx],   v[kx]);
                    ull vv1 = pk2(v[kx+1], v[kx+1]);
                    acc0[0] = fma2(vv0, w01.x, acc0[0]); acc1[0] = fma2(vv1, w01.x, acc1[0]);
                    acc0[1] = fma2(vv0, w01.y, acc0[1]); acc1[1] = fma2(vv1, w01.y, acc1[1]);
                    acc0[2] = fma2(vv0, w23.x, acc0[2]); acc1[2] = fma2(vv1, w23.x, acc1[2]);
                    acc0[3] = fma2(vv0, w23.y, acc0[3]); acc1[3] = fma2(vv1, w23.y, acc1[3]);
                    acc0[4] = fma2(vv0, w45.x, acc0[4]); acc1[4] = fma2(vv1, w45.x, acc1[4]);
                    acc0[5] = fma2(vv0, w45.y, acc0[5]); acc1[5] = fma2(vv1, w45.y, acc1[5]);
                    acc0[6] = fma2(vv0, w67.x, acc0[6]); acc1[6] = fma2(vv1, w67.x, acc1[6]);
                    acc0[7] = fma2(vv0, w67.y, acc0[7]); acc1[7] = fma2(vv1, w67.y, acc1[7]);
                    acc0[8] = fma2(vv0, w8,    acc0[8]); acc1[8] = fma2(vv1, w8,    acc1[8]);
                }
            }
        }
    }

    // epilogue: PReLU + bilinear param derivation
    float a = __ldg(&pa[0]);
    int yy = y0 + ty;
#pragma unroll
    for (int e = 0; e < 2; ++e){
        int xx = x0 + txq + e;
#pragma unroll
        for (int k = 0; k < 9; ++k){
            float dy, dx;
            unpk2(e ? acc1[k] : acc0[k], dy, dx);
            dy = dy > 0.f ? dy : a*dy;
            dx = dx > 0.f ? dx : a*dx;
            float py  = (float)yy + (float)(k/3 - 1) + dy;
            float pxx = (float)xx + (float)(k%3 - 1) + dx;
            float y0f = floorf(py), x0f = floorf(pxx);
            float fy = py - y0f, fx = pxx - x0f;
            float vy0 = (y0f >=  0.f && y0f <= 127.f) ? 1.f : 0.f;
            float vy1 = (y0f >= -1.f && y0f <= 126.f) ? 1.f : 0.f;
            float vx0 = (x0f >=  0.f && x0f <= 127.f) ? 1.f : 0.f;
            float vx1 = (x0f >= -1.f && x0f <= 126.f) ? 1.f : 0.f;
            float4 w;
            w.x = (1.f-fy)*(1.f-fx)*vy0*vx0;
            w.y = (1.f-fy)*fx*vy0*vx1;
            w.z = fy*(1.f-fx)*vy1*vx0;
            w.w = fy*fx*vy1*vx1;
            int y0i = (int)y0f, x0i = (int)x0f;
            int yc0 = min(max(y0i,   0), 127), yc1 = min(max(y0i+1, 0), 127);
            int xc0 = min(max(x0i,   0), 127), xc1 = min(max(x0i+1, 0), 127);
            unsigned lin00 = (unsigned)(yc0*128 + xc0);
            unsigned lin11 = (unsigned)(yc1*128 + xc1);
            size_t idx = ((size_t)(b*128 + yy)*9 + k)*128 + xx;
            g_bw[idx] = w;
            g_bi[idx] = lin00 | (lin11 << 16);
        }
    }
}

// ---------------------------------------------------------------
// Kernel 2: deformable grouped conv. Block 256 thr = 64 px of one row.
//  A) warp = 2px x 16 quads, j=0..3: param LDG (broadcast), 4 coalesced
//     float4 corner gathers from NHWC, combine, STS.128.
//  B) warp = group g, lane -> px (lane, lane+32): broadcast LDS.128
//     weights from smem, private 8-cig accumulation for 2 px.
// ---------------------------------------------------------------
__global__ __launch_bounds__(256) void k_deform(const float* __restrict__ dw,
                                                const float* __restrict__ db,
                                                float* __restrict__ out)
{
    __shared__ __align__(16) float s_w[4608];    // [k][g][cig][o8]
    __shared__ __align__(16) float s_buf[64*68]; // samples [p][68] / out [o][68]

    int tid = threadIdx.x;
    int lane = tid & 31, wid = tid >> 5;
    int b = blockIdx.z, y = blockIdx.y, x0 = blockIdx.x*64;

    // stage deform weights with transpose (coalesced LDG)
    for (int i = tid; i < 4608; i += 256){
        float v = __ldg(&dw[i]);
        int o = i / 72, r = i - o*72;
        int cig = r / 9, k = r - cig*9;
        s_w[((k*8 + (o>>3))*8 + cig)*8 + (o&7)] = v;
    }
    __syncthreads();

    int q = lane & 15, ph = lane >> 4;   // phase-A identity
    int g = wid;                          // phase-B identity
    int p0 = lane, p1 = lane + 32;

    const float4* xb = reinterpret_cast<const float4*>(g_xT) + (size_t)b*(128*128*16);
    size_t rowp = ((size_t)(b*128 + y))*9;

    ull acc[8] = {0,0,0,0,0,0,0,0};

#pragma unroll 1
    for (int k = 0; k < 9; ++k){
        size_t kbase = (rowp + k)*128;
        // ---- phase A: gather + combine -> s_buf ----
#pragma unroll
        for (int j = 0; j < 4; ++j){
            int p = wid*8 + j*2 + ph;
            int xg = x0 + p;
            float4 w = __ldg(&g_bw[kbase + xg]);
            unsigned bi = __ldg(&g_bi[kbase + xg]);
            int lin00 = bi & 0xFFFFu, lin11 = bi >> 16;
            int xc0 = lin00 & 127, xc1 = lin11 & 127;
            int y0b = lin00 - xc0, y1b = lin11 - xc1;
            float4 c00 = __ldg(&xb[(y0b + xc0)*16 + q]);
            float4 c01 = __ldg(&xb[(y0b + xc1)*16 + q]);
            float4 c10 = __ldg(&xb[(y1b + xc0)*16 + q]);
            float4 c11 = __ldg(&xb[(y1b + xc1)*16 + q]);
            float4 s;
            s.x = w.x*c00.x + w.y*c01.x + w.z*c10.x + w.w*c11.x;
            s.y = w.x*c00.y + w.y*c01.y + w.z*c10.y + w.w*c11.y;
            s.z = w.x*c00.z + w.y*c01.z + w.z*c10.z + w.w*c11.z;
            s.w = w.x*c00.w + w.y*c01.w + w.z*c10.w + w.w*c11.w;
            *reinterpret_cast<float4*>(&s_buf[p*68 + 4*q]) = s;
        }
        __syncthreads();
        // ---- phase B: broadcast weights, 2 px/thread ----
        {
            float4 s0a = *reinterpret_cast<const float4*>(&s_buf[p0*68 + g*8]);
            float4 s0b = *reinterpret_cast<const float4*>(&s_buf[p0*68 + g*8 + 4]);
            float4 s1a = *reinterpret_cast<const float4*>(&s_buf[p1*68 + g*8]);
            float4 s1b = *reinterpret_cast<const float4*>(&s_buf[p1*68 + g*8 + 4]);
            float sm0[8] = {s0a.x,s0a.y,s0a.z,s0a.w, s0b.x,s0b.y,s0b.z,s0b.w};
            float sm1[8] = {s1a.x,s1a.y,s1a.z,s1a.w, s1b.x,s1b.y,s1b.z,s1b.w};
            const ulonglong2* wk = reinterpret_cast<const ulonglong2*>(&s_w[(k*8 + g)*64]);
#pragma unroll
            for (int cig = 0; cig < 8; ++cig){
                ulonglong2 wab = wk[cig*2];
                ulonglong2 wcd = wk[cig*2+1];
                ull vv0 = pk2(sm0[cig], sm0[cig]);
                ull vv1 = pk2(sm1[cig], sm1[cig]);
                acc[0] = fma2(vv0, wab.x, acc[0]);
                acc[1] = fma2(vv0, wab.y, acc[1]);
                acc[2] = fma2(vv0, wcd.x, acc[2]);
                acc[3] = fma2(vv0, wcd.y, acc[3]);
                acc[4] = fma2(vv1, wab.x, acc[4]);
                acc[5] = fma2(vv1, wab.y, acc[5]);
                acc[6] = fma2(vv1, wcd.x, acc[6]);
                acc[7] = fma2(vv1, wcd.y, acc[7]);
            }
        }
        __syncthreads();
    }

    // stage outputs [o][68] and coalesced NCHW writeback
#pragma unroll
    for (int op = 0; op < 4; ++op){
        float lo, hi;
        unpk2(acc[op], lo, hi);
        s_buf[(g*8 + 2*op    )*68 + p0] = lo;
        s_buf[(g*8 + 2*op + 1)*68 + p0] = hi;
        unpk2(acc[4+op], lo, hi);
        s_buf[(g*8 + 2*op    )*68 + p1] = lo;
        s_buf[(g*8 + 2*op + 1)*68 + p1] = hi;
    }
    __syncthreads();
    for (int i = tid; i < 1024; i += 256){
        int o = i >> 4, p4 = (i & 15)*4;
        float bias = __ldg(&db[o]);
        float4 v = *reinterpret_cast<const float4*>(&s_buf[o*68 + p4]);
        v.x += bias; v.y += bias; v.z += bias; v.w += bias;
        *reinterpret_cast<float4*>(
            &out[((size_t)(b*64 + o)*128 + y)*128 + x0 + p4]) = v;
    }
}

extern "C" void kernel_launch(void* const* d_in, const int* in_sizes, int n_in,
                              void* d_out, int out_size)
{
    const float* x  = (const float*)d_in[0];
    const float* ow = (const float*)d_in[1];
    const float* ob = (const float*)d_in[2];
    const float* pa = (const float*)d_in[3];
    const float* dw = (const float*)d_in[4];
    const float* db = (const float*)d_in[5];
    float* out = (float*)d_out;

    k_offset<<<dim3(4, 8, 8), 256>>>(x, ow, ob, pa);
    k_deform<<<dim3(2, 128, 8), 256>>>(dw, db, out);
}

// round 7
// speedup vs baseline: 1.1595x; 1.0263x over previous
#include <cuda_runtime.h>
#include <cstdint>

typedef unsigned long long ull;

__device__ float  g_xT[8*128*128*64];     // NHWC copy of x
__device__ float4 g_bw[8*128*9*128];      // bilinear corner weights [b][y][k][x]
__device__ unsigned g_bi[8*128*9*128];    // packed lin00 | lin11<<16

static __device__ __forceinline__ ull pk2(float lo, float hi){
    ull r; asm("mov.b64 %0, {%1, %2};" : "=l"(r) : "f"(lo), "f"(hi)); return r;
}
static __device__ __forceinline__ void unpk2(ull v, float& lo, float& hi){
    asm("mov.b64 {%0, %1}, %2;" : "=f"(lo), "=f"(hi) : "l"(v));
}
static __device__ __forceinline__ ull fma2(ull a, ull b, ull c){
    ull d; asm("fma.rn.f32x2 %0, %1, %2, %3;" : "=l"(d) : "l"(a), "l"(b), "l"(c)); return d;
}

// ---------------------------------------------------------------
// Kernel 1: offset conv 64->18 + bias + PReLU -> bilinear params,
// plus NHWC emit of x. 128 thr = 32x8 px tile, 2 px/thread.
// Channel chunks of 8, register-buffered pipeline, 1 bar/chunk.
// ---------------------------------------------------------------
__global__ __launch_bounds__(128) void k_offset(const float* __restrict__ x,
                                                const float* __restrict__ ow,
                                                const float* __restrict__ ob,
                                                const float* __restrict__ pa)
{
    __shared__ float tile[2][2720];            // [c(8)][r(10)][col(34)]
    __shared__ __align__(16) ull wch[2][720];  // [(c*9+k)][10 ull rows]

    int tid = threadIdx.x;
    int ty = tid >> 4, txq = (tid & 15) * 2;
    int x0 = blockIdx.x*32, y0 = blockIdx.y*8, b = blockIdx.z;

    // staging descriptors (chunk-invariant)
    int t_off[22]; unsigned tmask = 0;
#pragma unroll
    for (int s = 0; s < 22; ++s){
        int i = tid + s*128;
        int c = i / 340, rr = i - c*340;
        int r = rr / 34, col = rr - r*34;
        int gy = y0 - 1 + r, gx = x0 - 1 + col;
        t_off[s] = c*16384 + gy*128 + gx;
        if (i < 2720 && (unsigned)gy < 128u && (unsigned)gx < 128u) tmask |= (1u << s);
    }
    int w_src[11], w_dst[11];
#pragma unroll
    for (int s = 0; s < 11; ++s){
        int i = tid + s*128;
        int oc = i / 72, r = i - oc*72;
        w_src[s] = (i < 1296) ? (oc*576 + r) : -1;
        w_dst[s] = r*20 + oc;   // pitch 10 ull = 20 floats
    }
    const float* xb = x + (size_t)b*(64*16384);

    ull acc0[9], acc1[9];
#pragma unroll
    for (int o9 = 0; o9 < 9; ++o9){
        ull b2 = pk2(__ldg(&ob[2*o9]), __ldg(&ob[2*o9+1]));
        acc0[o9] = b2; acc1[o9] = b2;
    }

    // prologue: stage chunk 0 directly
#pragma unroll
    for (int s = 0; s < 11; ++s)
        if (w_src[s] >= 0)
            reinterpret_cast<float*>(wch[0])[w_dst[s]] = __ldg(&ow[w_src[s]]);
#pragma unroll
    for (int s = 0; s < 22; ++s){
        int i = tid + s*128;
        if (i < 2720)
            tile[0][i] = (tmask >> s & 1u) ? __ldg(&xb[t_off[s]]) : 0.f;
    }

    for (int ch = 0; ch < 8; ++ch){
        __syncthreads();
        int bf = ch & 1;
        // issue next chunk's loads into registers (latency hidden by compute)
        float wv[11], tv[22];
        if (ch < 7){
            int c0n = (ch+1)*8;
#pragma unroll
            for (int s = 0; s < 11; ++s)
                wv[s] = (w_src[s] >= 0) ? __ldg(&ow[w_src[s] + c0n*9]) : 0.f;
#pragma unroll
            for (int s = 0; s < 22; ++s)
                tv[s] = (tmask >> s & 1u) ? __ldg(&xb[t_off[s] + c0n*16384]) : 0.f;
        }

        // NHWC emit for this chunk
        int c0 = ch*8;
#pragma unroll
        for (int e = 0; e < 2; ++e){
            int base = (ty+1)*34 + (txq+1+e);
            float4 lo4, hi4;
            lo4.x = tile[bf][0*340+base]; lo4.y = tile[bf][1*340+base];
            lo4.z = tile[bf][2*340+base]; lo4.w = tile[bf][3*340+base];
            hi4.x = tile[bf][4*340+base]; hi4.y = tile[bf][5*340+base];
            hi4.z = tile[bf][6*340+base]; hi4.w = tile[bf][7*340+base];
            float4* dst = reinterpret_cast<float4*>(
                g_xT + ((size_t)(b*128 + y0+ty)*128 + x0+txq+e)*64 + c0);
            dst[0] = lo4; dst[1] = hi4;
        }

        // conv accumulate (2 px share every weight load)
        for (int c = 0; c < 8; ++c){
#pragma unroll
            for (int ky = 0; ky < 3; ++ky){
                int rbase = c*340 + (ty+ky)*34 + txq;
                float2 va = *reinterpret_cast<const float2*>(&tile[bf][rbase]);
                float2 vb = *reinterpret_cast<const float2*>(&tile[bf][rbase+2]);
                float v[4] = {va.x, va.y, vb.x, vb.y};
#pragma unroll
                for (int kx = 0; kx < 3; ++kx){
                    const ulonglong2* wp2 = reinterpret_cast<const ulonglong2*>(
                        &wch[bf][(c*9 + ky*3 + kx)*10]);
                    ulonglong2 w01 = wp2[0], w23 = wp2[1], w45 = wp2[2], w67 = wp2[3];
                    ull w8 = wch[bf][(c*9 + ky*3 + kx)*10 + 8];
                    ull vv0 = pk2(v[kx],   v[kx]);
                    ull vv1 = pk2(v[kx+1], v[kx+1]);
                    acc0[0] = fma2(vv0, w01.x, acc0[0]); acc1[0] = fma2(vv1, w01.x, acc1[0]);
                    acc0[1] = fma2(vv0, w01.y, acc0[1]); acc1[1] = fma2(vv1, w01.y, acc1[1]);
                    acc0[2] = fma2(vv0, w23.x, acc0[2]); acc1[2] = fma2(vv1, w23.x, acc1[2]);
                    acc0[3] = fma2(vv0, w23.y, acc0[3]); acc1[3] = fma2(vv1, w23.y, acc1[3]);
                    acc0[4] = fma2(vv0, w45.x, acc0[4]); acc1[4] = fma2(vv1, w45.x, acc1[4]);
                    acc0[5] = fma2(vv0, w45.y, acc0[5]); acc1[5] = fma2(vv1, w45.y, acc1[5]);
                    acc0[6] = fma2(vv0, w67.x, acc0[6]); acc1[6] = fma2(vv1, w67.x, acc1[6]);
                    acc0[7] = fma2(vv0, w67.y, acc0[7]); acc1[7] = fma2(vv1, w67.y, acc1[7]);
                    acc0[8] = fma2(vv0, w8,    acc0[8]); acc1[8] = fma2(vv1, w8,    acc1[8]);
                }
            }
        }

        // STS next chunk into the other buffers
        if (ch < 7){
            int nb = bf ^ 1;
#pragma unroll
            for (int s = 0; s < 11; ++s)
                if (w_src[s] >= 0)
                    reinterpret_cast<float*>(wch[nb])[w_dst[s]] = wv[s];
#pragma unroll
            for (int s = 0; s < 22; ++s){
                int i = tid + s*128;
                if (i < 2720) tile[nb][i] = tv[s];
            }
        }
    }

    // epilogue: PReLU + bilinear param derivation
    float a = __ldg(&pa[0]);
    int yy = y0 + ty;
#pragma unroll
    for (int e = 0; e < 2; ++e){
        int xx = x0 + txq + e;
#pragma unroll
        for (int k = 0; k < 9; ++k){
            float dy, dx;
            unpk2(e ? acc1[k] : acc0[k], dy, dx);
            dy = dy > 0.f ? dy : a*dy;
            dx = dx > 0.f ? dx : a*dx;
            float py  = (float)yy + (float)(k/3 - 1) + dy;
            float pxx = (float)xx + (float)(k%3 - 1) + dx;
            float y0f = floorf(py), x0f = floorf(pxx);
            float fy = py - y0f, fx = pxx - x0f;
            float vy0 = (y0f >=  0.f && y0f <= 127.f) ? 1.f : 0.f;
            float vy1 = (y0f >= -1.f && y0f <= 126.f) ? 1.f : 0.f;
            float vx0 = (x0f >=  0.f && x0f <= 127.f) ? 1.f : 0.f;
            float vx1 = (x0f >= -1.f && x0f <= 126.f) ? 1.f : 0.f;
            float4 w;
            w.x = (1.f-fy)*(1.f-fx)*vy0*vx0;
            w.y = (1.f-fy)*fx*vy0*vx1;
            w.z = fy*(1.f-fx)*vy1*vx0;
            w.w = fy*fx*vy1*vx1;
            int y0i = (int)y0f, x0i = (int)x0f;
            int yc0 = min(max(y0i,   0), 127), yc1 = min(max(y0i+1, 0), 127);
            int xc0 = min(max(x0i,   0), 127), xc1 = min(max(x0i+1, 0), 127);
            unsigned lin00 = (unsigned)(yc0*128 + xc0);
            unsigned lin11 = (unsigned)(yc1*128 + xc1);
            size_t idx = ((size_t)(b*128 + yy)*9 + k)*128 + xx;
            g_bw[idx] = w;
            g_bi[idx] = lin00 | (lin11 << 16);
        }
    }
}

// ---------------------------------------------------------------
// Kernel 2: deformable grouped conv, software-pipelined, all-static
// smem (35 KB). Block 128 thr = 32 px of one row; double-buffered
// sample smem; ONE barrier per k.
//  A) warp = 2px x 16 quads (j=0..3): param LDG, coalesced float4
//     corner gathers, combine, STS.128.
//  B) thread = pixel (lane), warp owns groups 2w,2w+1: broadcast
//     LDS.128 weights, private 8-cig accumulation, direct coalesced
//     STG.32 epilogue (no restage).
// ---------------------------------------------------------------
__global__ __launch_bounds__(128) void k_deform(const float* __restrict__ dw,
                                                const float* __restrict__ db,
                                                float* __restrict__ out)
{
    __shared__ __align__(16) float s_w[4608];       // [k][g][cig][o8]
    __shared__ __align__(16) float s_buf[2][2176];  // samples [p(32)][68]

    int tid = threadIdx.x;
    int lane = tid & 31, wid = tid >> 5;
    int b = blockIdx.z, y = blockIdx.y, x0 = blockIdx.x*32;

    // stage deform weights with transpose (coalesced LDG)
    for (int i = tid; i < 4608; i += 128){
        float v = __ldg(&dw[i]);
        int o = i / 72, r = i - o*72;
        int cig = r / 9, k = r - cig*9;
        s_w[((k*8 + (o>>3))*8 + cig)*8 + (o&7)] = v;
    }

    int q = lane & 15, ph = lane >> 4;    // phase-A identity
    int g0 = wid*2, g1 = wid*2 + 1;       // phase-B identity
    int p = lane;

    const float4* xb = reinterpret_cast<const float4*>(g_xT) + (size_t)b*(128*128*16);
    size_t rowp = ((size_t)(b*128 + y))*9;

    ull acc[8] = {0,0,0,0,0,0,0,0};       // [group(2)][opair(4)]

    auto gather = [&](int kk, float* buf){
        size_t kbase = (rowp + kk)*128;
#pragma unroll
        for (int j = 0; j < 4; ++j){
            int pp = wid*8 + j*2 + ph;
            int xg = x0 + pp;
            float4 w = __ldg(&g_bw[kbase + xg]);
            unsigned bi = __ldg(&g_bi[kbase + xg]);
            int lin00 = bi & 0xFFFFu, lin11 = bi >> 16;
            int xc0 = lin00 & 127, xc1 = lin11 & 127;
            int y0b = lin00 - xc0, y1b = lin11 - xc1;
            float4 c00 = __ldg(&xb[(y0b + xc0)*16 + q]);
            float4 c01 = __ldg(&xb[(y0b + xc1)*16 + q]);
            float4 c10 = __ldg(&xb[(y1b + xc0)*16 + q]);
            float4 c11 = __ldg(&xb[(y1b + xc1)*16 + q]);
            float4 s;
            s.x = w.x*c00.x + w.y*c01.x + w.z*c10.x + w.w*c11.x;
            s.y = w.x*c00.y + w.y*c01.y + w.z*c10.y + w.w*c11.y;
            s.z = w.x*c00.z + w.y*c01.z + w.z*c10.z + w.w*c11.z;
            s.w = w.x*c00.w + w.y*c01.w + w.z*c10.w + w.w*c11.w;
            *reinterpret_cast<float4*>(&buf[pp*68 + 4*q]) = s;
        }
    };

    __syncthreads();          // weights staged
    gather(0, s_buf[0]);

#pragma unroll 1
    for (int k = 0; k < 9; ++k){
        __syncthreads();      // buf[k&1] full; prior gemm reads done
        const float* cur = s_buf[k & 1];
        {
            float4 a0 = *reinterpret_cast<const float4*>(&cur[p*68 + g0*8]);
            float4 a1 = *reinterpret_cast<const float4*>(&cur[p*68 + g0*8 + 4]);
            float4 b0 = *reinterpret_cast<const float4*>(&cur[p*68 + g1*8]);
            float4 b1 = *reinterpret_cast<const float4*>(&cur[p*68 + g1*8 + 4]);
            float sm0[8] = {a0.x,a0.y,a0.z,a0.w, a1.x,a1.y,a1.z,a1.w};
            float sm1[8] = {b0.x,b0.y,b0.z,b0.w, b1.x,b1.y,b1.z,b1.w};
            const ulonglong2* wk0 = reinterpret_cast<const ulonglong2*>(&s_w[(k*8 + g0)*64]);
            const ulonglong2* wk1 = reinterpret_cast<const ulonglong2*>(&s_w[(k*8 + g1)*64]);
#pragma unroll
            for (int cig = 0; cig < 8; ++cig){
                ulonglong2 wa = wk0[cig*2], wb = wk0[cig*2+1];
                ulonglong2 wc = wk1[cig*2], wd = wk1[cig*2+1];
                ull vv0 = pk2(sm0[cig], sm0[cig]);
                ull vv1 = pk2(sm1[cig], sm1[cig]);
                acc[0] = fma2(vv0, wa.x, acc[0]);
                acc[1] = fma2(vv0, wa.y, acc[1]);
                acc[2] = fma2(vv0, wb.x, acc[2]);
                acc[3] = fma2(vv0, wb.y, acc[3]);
                acc[4] = fma2(vv1, wc.x, acc[4]);
                acc[5] = fma2(vv1, wc.y, acc[5]);
                acc[6] = fma2(vv1, wd.x, acc[6]);
                acc[7] = fma2(vv1, wd.y, acc[7]);
            }
        }
        if (k < 8) gather(k+1, s_buf[(k+1) & 1]);
    }

    // epilogue: direct coalesced stores (lane = pixel -> consecutive x)
    float* orow = out + ((size_t)b*64*128 + y)*128 + x0 + p;
#pragma unroll
    for (int gg = 0; gg < 2; ++gg){
        int gb = (gg ? g1 : g0) * 8;
#pragma unroll
        for (int op = 0; op < 4; ++op){
            float lo, hi;
            unpk2(acc[gg*4 + op], lo, hi);
            int o0 = gb + 2*op;
            orow[(size_t)o0*16384]       = lo + __ldg(&db[o0]);
            orow[(size_t)(o0+1)*16384]   = hi + __ldg(&db[o0+1]);
        }
    }
}

extern "C" void kernel_launch(void* const* d_in, const int* in_sizes, int n_in,
                              void* d_out, int out_size)
{
    const float* x  = (const float*)d_in[0];
    const float* ow = (const float*)d_in[1];
    const float* ob = (const float*)d_in[2];
    const float* pa = (const float*)d_in[3];
    const float* dw = (const float*)d_in[4];
    const float* db = (const float*)d_in[5];
    float* out = (float*)d_out;

    k_offset<<<dim3(4, 16, 8), 128>>>(x, ow, ob, pa);
    k_deform<<<dim3(4, 128, 8), 128>>>(dw, db, out);
}